// round 3
// baseline (speedup 1.0000x reference)
#include <cuda_runtime.h>
#include <cstdint>

// Problem constants
#define BS 4096
#define D  100
#define H  16
#define P  2

#define BATCHES_PER_BLOCK 2
#define THREADS 256
#define XM_STRIDE 104          // floats per row: 16B-aligned, conflict-free store tiling

// Shared memory layout (floats).
// h1/h2 buffers live INSIDE the xm regions: xm is dead after Phase B reads it,
// and Phase B writes h1 only after a __syncthreads() — but h1 writes overlap
// Phase B's own xm reads, so h1/h2 must NOT alias xm rows still being read.
// Safe placement: put h1/h2 in the TAIL of xmB's region is unsafe (Phase B reads
// all of xmA and xmB). Instead h1A/h1B are written during Phase B — so they get
// their own small region; only h2 reuses xm space (Phase C runs after a sync,
// xm fully dead). Layout:
//   [0             .. 10400)  xmA
//   [10400         .. 20800)  xmB
//   [20800         .. 20900)  xsA
//   [20900         .. 21000)  xsB
//   [0             ..  1600)  h2A  (reuses xmA after sync; Phase C writes, Phase D reads)
//   [1600          ..  3200)  h2B  (reuses xmA)
//   [21000         .. 22600)  h1A
//   [22600         .. 24200)  h1B
#define OFF_XMA   0
#define OFF_XMB   (OFF_XMA + D * XM_STRIDE)       // 10400
#define OFF_XSA   (OFF_XMB + D * XM_STRIDE)       // 20800
#define OFF_XSB   (OFF_XSA + D)                   // 20900
#define OFF_H1A   (OFF_XSB + D)                   // 21000
#define OFF_H1B   (OFF_H1A + D * H)               // 22600
#define OFF_H2A   0                               // aliases xmA (dead by Phase C)
#define OFF_H2B   (D * H)                         // 1600, still inside xmA region
#define SMEM_FLOATS (OFF_H1B + D * H)             // 24200
#define SMEM_BYTES (SMEM_FLOATS * 4)              // 96800

__device__ __forceinline__ float leaky(float v) {
    // slope 0.01: for v>0, v > 0.01v; for v<0, 0.01v > v  -> fmaxf is exact
    return fmaxf(v, 0.01f * v);
}

__device__ __forceinline__ float dot4(float4 a, float4 b) {
    float r = a.x * b.x;
    r = fmaf(a.y, b.y, r);
    r = fmaf(a.z, b.z, r);
    r = fmaf(a.w, b.w, r);
    return r;
}

__global__ __launch_bounds__(THREADS, 2)
void basemodel_kernel(const float* __restrict__ x,
                      const float* __restrict__ log_alpha,
                      const float* __restrict__ noise,
                      const float* __restrict__ W0,
                      const float* __restrict__ b0,
                      const float* __restrict__ W1,
                      const float* __restrict__ b1,
                      const float* __restrict__ W2,
                      const float* __restrict__ b2,
                      float* __restrict__ out)
{
    extern __shared__ float sm[];
    float* xmA = sm + OFF_XMA;
    float* xmB = sm + OFF_XMB;
    float* xsA = sm + OFF_XSA;
    float* xsB = sm + OFF_XSB;
    float* h1A = sm + OFF_H1A;
    float* h1B = sm + OFF_H1B;
    float* h2A = sm + OFF_H2A;
    float* h2B = sm + OFF_H2B;

    const int tid  = threadIdx.x;
    const int lane = tid & 31;
    const int warp = tid >> 5;

    const int bA = blockIdx.x * BATCHES_PER_BLOCK;
    const int bB = bA + 1;

    const float* xA  = x + (size_t)bA * D;
    const float* xB  = x + (size_t)bB * D;
    const float* nzA = noise + (size_t)bA * D * D;
    const float* nzB = noise + (size_t)bB * D * D;

    // ---- Stage x into shared ----
    if (tid < D)                          xsA[tid]       = xA[tid];
    else if (tid >= 128 && tid < 128 + D) xsB[tid - 128] = xB[tid - 128];
    __syncthreads();

    // ---- Phase A: build masked, transposed inputs xm[t][j] ----
    // Forward value of the straight-through estimator is exactly y_hard:
    //   keep x[j] iff (log_alpha[j,t] + noise[b,j,t]) > 0 and j != t.
    // Warp tile: 8 j-rows x 4 t-cols. Store bank = (104*t + j) mod 32
    //   = (8*dt + dj) mod 32 over dt in 0..3, dj in 0..7 -> all 32 distinct.
    for (int m = warp; m < 13 * 25; m += (THREADS / 32)) {
        int jb = m / 25;
        int tb = m - jb * 25;
        int j  = jb * 8 + (lane >> 2);
        int t  = tb * 4 + (lane & 3);
        if (j < D) {
            int idxn = j * D + t;
            float la = log_alpha[idxn];
            float nA = nzA[idxn];
            float nB = nzB[idxn];
            bool offdiag = (j != t);
            float va = ((la + nA) > 0.0f && offdiag) ? xsA[j] : 0.0f;
            float vb = ((la + nB) > 0.0f && offdiag) ? xsB[j] : 0.0f;
            xmA[t * XM_STRIDE + j] = va;
            xmB[t * XM_STRIDE + j] = vb;
        }
    }
    __syncthreads();

    // ---- Phase B: layer0  h1[t][i] = leaky(W0[t,i,:] . xm[t][:] + b0[t,i]) ----
    // One thread per (t,i); 2 accumulators share each W0 float4 fetch.
    for (int idx = tid; idx < D * H; idx += THREADS) {
        int t = idx >> 4;
        const float4* w4 = reinterpret_cast<const float4*>(W0 + (size_t)idx * D);
        const float4* a4 = reinterpret_cast<const float4*>(xmA + t * XM_STRIDE);
        const float4* c4 = reinterpret_cast<const float4*>(xmB + t * XM_STRIDE);
        float accA = 0.0f, accB = 0.0f;
        #pragma unroll 5
        for (int g = 0; g < D / 4; ++g) {
            float4 w = w4[g];
            float4 a = a4[g];
            float4 c = c4[g];
            accA = fmaf(w.x, a.x, accA); accA = fmaf(w.y, a.y, accA);
            accA = fmaf(w.z, a.z, accA); accA = fmaf(w.w, a.w, accA);
            accB = fmaf(w.x, c.x, accB); accB = fmaf(w.y, c.y, accB);
            accB = fmaf(w.z, c.z, accB); accB = fmaf(w.w, c.w, accB);
        }
        float bias = b0[idx];
        h1A[idx] = leaky(accA + bias);
        h1B[idx] = leaky(accB + bias);
    }
    __syncthreads();   // xm now dead; h2 regions (aliasing xmA) become writable

    // ---- Phase C: layer1  h2[t][i] = leaky(W1[t,i,:] . h1[t][:] + b1[t,i]) ----
    for (int idx = tid; idx < D * H; idx += THREADS) {
        int t = idx >> 4;
        int i = idx & 15;
        const float4* w4  = reinterpret_cast<const float4*>(W1 + (size_t)t * H * H + i * H);
        const float4* ha4 = reinterpret_cast<const float4*>(h1A + t * H);
        const float4* hb4 = reinterpret_cast<const float4*>(h1B + t * H);
        float accA = 0.0f, accB = 0.0f;
        #pragma unroll
        for (int g = 0; g < H / 4; ++g) {
            float4 w = w4[g];
            accA += dot4(w, ha4[g]);
            accB += dot4(w, hb4[g]);
        }
        float bias = b1[idx];
        h2A[idx] = leaky(accA + bias);
        h2B[idx] = leaky(accB + bias);
    }
    __syncthreads();

    // ---- Phase D: output  out[b,t,p] = W2[t,p,:] . h2[t][:] + b2[t,p] ----
    if (tid < D * P) {
        int t = tid >> 1;
        int p = tid & 1;
        const float4* w4  = reinterpret_cast<const float4*>(W2 + (size_t)t * P * H + p * H);
        const float4* ha4 = reinterpret_cast<const float4*>(h2A + t * H);
        const float4* hb4 = reinterpret_cast<const float4*>(h2B + t * H);
        float accA = 0.0f, accB = 0.0f;
        #pragma unroll
        for (int g = 0; g < H / 4; ++g) {
            float4 w = w4[g];
            accA += dot4(w, ha4[g]);
            accB += dot4(w, hb4[g]);
        }
        float bias = b2[tid];
        out[(size_t)bA * D * P + tid] = accA + bias;
        out[(size_t)bB * D * P + tid] = accB + bias;
    }
}

extern "C" void kernel_launch(void* const* d_in, const int* in_sizes, int n_in,
                              void* d_out, int out_size)
{
    const float* x         = (const float*)d_in[0];
    const float* log_alpha = (const float*)d_in[1];
    const float* noise     = (const float*)d_in[2];
    const float* W0        = (const float*)d_in[3];
    const float* b0        = (const float*)d_in[4];
    const float* W1        = (const float*)d_in[5];
    const float* b1        = (const float*)d_in[6];
    const float* W2        = (const float*)d_in[7];
    const float* b2        = (const float*)d_in[8];
    float* out             = (float*)d_out;

    cudaFuncSetAttribute(basemodel_kernel,
                         cudaFuncAttributeMaxDynamicSharedMemorySize, SMEM_BYTES);

    dim3 grid(BS / BATCHES_PER_BLOCK);
    dim3 block(THREADS);
    basemodel_kernel<<<grid, block, SMEM_BYTES>>>(
        x, log_alpha, noise, W0, b0, W1, b1, W2, b2, out);
}

// round 4
// speedup vs baseline: 2.2949x; 2.2949x over previous
#include <cuda_runtime.h>
#include <cstdint>

// Problem constants
#define BS 4096
#define D  100
#define H  16
#define P  2

#define BPB 4            // batches per block (vectorized as float4)
#define THREADS 512
#define GRID (BS / BPB)  // 1024

// ---------------- device scratch (allocation-free rule: __device__ globals) ----
// W0T4[(g*100 + t)*16 + i] = float4{ W0[t,i,4g+0..3] }   (g = j/4)
__device__ float4 g_W0T4[25 * D * H];        // 40000 float4 = 640 KB
// W1T[(t*16 + j)*16 + i] = W1[t,i,j]
__device__ float  g_W1T[D * H * H];          // 25600 floats = 102.4 KB

// ---------------- shared memory layout (bytes) ----------------
// xm4 : 10000 float4 = 160000   (xm4[j*100 + t] = float4 over 4 batches)
// h1_4:  1600 float4 =  25600
// h2_4: aliases xm4[0..1600)    (xm dead after Phase B)
// xs4 :   100 float4 =   1600
#define SMEM_XM4_F4   (D * D)          // 10000
#define SMEM_H1_F4    (D * H)          // 1600
#define SMEM_XS_F4    (D)              // 100
#define SMEM_BYTES    ((SMEM_XM4_F4 + SMEM_H1_F4 + SMEM_XS_F4) * 16)  // 187200

__device__ __forceinline__ float leaky1(float v) { return fmaxf(v, 0.01f * v); }
__device__ __forceinline__ float4 leaky4(float4 v) {
    return make_float4(leaky1(v.x), leaky1(v.y), leaky1(v.z), leaky1(v.w));
}

// ---------------- pre-pass: weight transposes (run every launch; deterministic) ----
__global__ void transpose_w0(const float* __restrict__ W0) {
    int m = blockIdx.x * blockDim.x + threadIdx.x;   // m = (g*100 + t)*16 + i
    if (m >= 25 * D * H) return;
    int g = m / (D * H);
    int r = m - g * (D * H);
    int t = r >> 4;
    int i = r & 15;
    const float4* src = reinterpret_cast<const float4*>(W0 + (size_t)(t * H + i) * D);
    g_W0T4[m] = src[g];                               // 16B-aligned: row = 400 B
}

__global__ void transpose_w1(const float* __restrict__ W1) {
    int m = blockIdx.x * blockDim.x + threadIdx.x;   // m = (t*16 + j)*16 + i
    if (m >= D * H * H) return;
    int i = m & 15;
    int j = (m >> 4) & 15;
    int t = m >> 8;
    g_W1T[m] = W1[(size_t)(t * H + i) * H + j];
}

// ---------------- main kernel: 1 CTA = 4 batches ----------------
__global__ __launch_bounds__(THREADS, 1)
void basemodel_kernel(const float* __restrict__ x,
                      const float* __restrict__ log_alpha,
                      const float* __restrict__ noise,
                      const float* __restrict__ b0,
                      const float* __restrict__ b1,
                      const float* __restrict__ W2,
                      const float* __restrict__ b2,
                      float* __restrict__ out)
{
    extern __shared__ float4 sm4[];
    float4* xm4  = sm4;                                // [j*100 + t], batch-vector
    float4* h1_4 = sm4 + SMEM_XM4_F4;                  // [t*16 + i]
    float4* h2_4 = sm4;                                // alias xm4 (dead after B)
    float4* xs4  = sm4 + SMEM_XM4_F4 + SMEM_H1_F4;     // [j], batch-vector

    const int tid = threadIdx.x;
    const int b0i = blockIdx.x * BPB;

    // ---- stage x (4 batches) ----
    if (tid < D) {
        const float* xp = x + (size_t)b0i * D + tid;
        xs4[tid] = make_float4(xp[0], xp[D], xp[2 * D], xp[3 * D]);
    }
    __syncthreads();

    // ---- Phase A: masked adjacency-gated inputs, fully linear in m = j*100 + t ----
    // Forward value of straight-through estimator == y_hard:
    //   keep x[b][j] iff (log_alpha[j,t] + noise[b,j,t]) > 0 and j != t.
    {
        const float* nz = noise + (size_t)b0i * D * D;
        for (int m = tid; m < D * D; m += THREADS) {
            int j = m / D;
            int t = m - j * D;
            float  la = log_alpha[m];
            float4 xv = xs4[j];
            bool   od = (j != t);
            float4 v;
            v.x = ((la + nz[m])             > 0.0f && od) ? xv.x : 0.0f;
            v.y = ((la + nz[m + D * D])     > 0.0f && od) ? xv.y : 0.0f;
            v.z = ((la + nz[m + 2 * D * D]) > 0.0f && od) ? xv.z : 0.0f;
            v.w = ((la + nz[m + 3 * D * D]) > 0.0f && od) ? xv.w : 0.0f;
            xm4[m] = v;   // coalesced STS.128, conflict-free
        }
    }
    __syncthreads();

    // ---- Phase B: layer0. thread-per-(t,i); W0T coalesced; xm broadcast LDS ----
    for (int idx = tid; idx < D * H; idx += THREADS) {
        int t = idx >> 4;
        float4 acc = make_float4(0.f, 0.f, 0.f, 0.f);
        #pragma unroll 5
        for (int g = 0; g < D / 4; ++g) {
            float4 w  = g_W0T4[(g * D) * H + idx - (idx >> 4 << 4) + (t << 4)]; // see note
            // note: (g*100 + t)*16 + i  ==  g*1600 + t*16 + i  ==  g*1600 + idx
            w = g_W0T4[g * (D * H) + idx];
            const float4* xr = xm4 + (4 * g) * D + t;
            float4 x0 = xr[0];
            float4 x1 = xr[D];
            float4 x2 = xr[2 * D];
            float4 x3 = xr[3 * D];
            acc.x = fmaf(w.x, x0.x, acc.x); acc.y = fmaf(w.x, x0.y, acc.y);
            acc.z = fmaf(w.x, x0.z, acc.z); acc.w = fmaf(w.x, x0.w, acc.w);
            acc.x = fmaf(w.y, x1.x, acc.x); acc.y = fmaf(w.y, x1.y, acc.y);
            acc.z = fmaf(w.y, x1.z, acc.z); acc.w = fmaf(w.y, x1.w, acc.w);
            acc.x = fmaf(w.z, x2.x, acc.x); acc.y = fmaf(w.z, x2.y, acc.y);
            acc.z = fmaf(w.z, x2.z, acc.z); acc.w = fmaf(w.z, x2.w, acc.w);
            acc.x = fmaf(w.w, x3.x, acc.x); acc.y = fmaf(w.w, x3.y, acc.y);
            acc.z = fmaf(w.w, x3.z, acc.z); acc.w = fmaf(w.w, x3.w, acc.w);
        }
        float bias = b0[idx];
        h1_4[idx] = leaky4(make_float4(acc.x + bias, acc.y + bias,
                                       acc.z + bias, acc.w + bias));
    }
    __syncthreads();   // xm4 now dead -> h2_4 (aliasing it) becomes writable

    // ---- Phase C: layer1 ----
    for (int idx = tid; idx < D * H; idx += THREADS) {
        int t = idx >> 4;
        int i = idx & 15;
        float4 acc = make_float4(0.f, 0.f, 0.f, 0.f);
        #pragma unroll
        for (int j = 0; j < H; ++j) {
            float  wv = g_W1T[(t * H + j) * H + i];
            float4 hv = h1_4[t * H + j];
            acc.x = fmaf(wv, hv.x, acc.x); acc.y = fmaf(wv, hv.y, acc.y);
            acc.z = fmaf(wv, hv.z, acc.z); acc.w = fmaf(wv, hv.w, acc.w);
        }
        float bias = b1[idx];
        h2_4[idx] = leaky4(make_float4(acc.x + bias, acc.y + bias,
                                       acc.z + bias, acc.w + bias));
    }
    __syncthreads();

    // ---- Phase D: output layer (tiny) ----
    if (tid < D * P) {
        int t = tid >> 1;
        const float4* w4 = reinterpret_cast<const float4*>(W2 + (size_t)tid * H);
        float4 acc = make_float4(0.f, 0.f, 0.f, 0.f);
        #pragma unroll
        for (int g = 0; g < H / 4; ++g) {
            float4 w = w4[g];
            float4 h0 = h2_4[t * H + 4 * g + 0];
            float4 h1v = h2_4[t * H + 4 * g + 1];
            float4 h2v = h2_4[t * H + 4 * g + 2];
            float4 h3 = h2_4[t * H + 4 * g + 3];
            acc.x = fmaf(w.x, h0.x, acc.x); acc.y = fmaf(w.x, h0.y, acc.y);
            acc.z = fmaf(w.x, h0.z, acc.z); acc.w = fmaf(w.x, h0.w, acc.w);
            acc.x = fmaf(w.y, h1v.x, acc.x); acc.y = fmaf(w.y, h1v.y, acc.y);
            acc.z = fmaf(w.y, h1v.z, acc.z); acc.w = fmaf(w.y, h1v.w, acc.w);
            acc.x = fmaf(w.z, h2v.x, acc.x); acc.y = fmaf(w.z, h2v.y, acc.y);
            acc.z = fmaf(w.z, h2v.z, acc.z); acc.w = fmaf(w.z, h2v.w, acc.w);
            acc.x = fmaf(w.w, h3.x, acc.x); acc.y = fmaf(w.w, h3.y, acc.y);
            acc.z = fmaf(w.w, h3.z, acc.z); acc.w = fmaf(w.w, h3.w, acc.w);
        }
        float bias = b2[tid];
        float* op = out + (size_t)b0i * D * P + tid;
        op[0]         = acc.x + bias;
        op[D * P]     = acc.y + bias;
        op[2 * D * P] = acc.z + bias;
        op[3 * D * P] = acc.w + bias;
    }
}

extern "C" void kernel_launch(void* const* d_in, const int* in_sizes, int n_in,
                              void* d_out, int out_size)
{
    const float* x         = (const float*)d_in[0];
    const float* log_alpha = (const float*)d_in[1];
    const float* noise     = (const float*)d_in[2];
    const float* W0        = (const float*)d_in[3];
    const float* b0        = (const float*)d_in[4];
    const float* W1        = (const float*)d_in[5];
    const float* b1        = (const float*)d_in[6];
    const float* W2        = (const float*)d_in[7];
    const float* b2        = (const float*)d_in[8];
    float* out             = (float*)d_out;

    // Weight transposes into __device__ scratch (graph-capturable kernel launches)
    transpose_w0<<<(25 * D * H + 255) / 256, 256>>>(W0);
    transpose_w1<<<(D * H * H + 255) / 256, 256>>>(W1);

    cudaFuncSetAttribute(basemodel_kernel,
                         cudaFuncAttributeMaxDynamicSharedMemorySize, SMEM_BYTES);

    basemodel_kernel<<<GRID, THREADS, SMEM_BYTES>>>(
        x, log_alpha, noise, b0, b1, W2, b2, out);
}

// round 7
// speedup vs baseline: 4.1873x; 1.8246x over previous
#include <cuda_runtime.h>
#include <cstdint>

#define BS 4096
#define D  100
#define H  16
#define P  2

#define BPB 8
#define THREADS 256
#define GRID (BS / BPB)          // 512

// ---- device scratch (allocation-free rule) ----
// W0T8[((g*100+t)*8+ip)*2 + {0,1}] = float4{ W0[t, 2ip+{0,1}, 4g..4g+3] }
__device__ float4 g_W0T8[2 * 25 * D * 8];     // 40000 float4 = 640 KB
// W1T2[(t*16+j)*8+ip] = { W1[t,2ip,j], W1[t,2ip+1,j] }
__device__ float2 g_W1T2[D * H * 8];          // 12800 float2 = 102.4 KB

__device__ __forceinline__ float leaky1(float v) { return fmaxf(v, 0.01f * v); }

// ---------------- prep: weight relayout (one kernel -> 2 launches/replay) ----
__global__ void prep_kernel(const float* __restrict__ W0,
                            const float* __restrict__ W1)
{
    int n = blockIdx.x * blockDim.x + threadIdx.x;
    if (n < 25 * D * 8) {                       // 20000: W0 relayout
        int g  = n / 800;
        int r  = n - g * 800;
        int t  = r >> 3;
        int ip = r & 7;
        const float4* lo = (const float4*)(W0 + (size_t)(t * 16 + 2 * ip) * D);
        const float4* hi = (const float4*)(W0 + (size_t)(t * 16 + 2 * ip + 1) * D);
        g_W0T8[2 * n]     = lo[g];
        g_W0T8[2 * n + 1] = hi[g];
    } else if (n < 25 * D * 8 + D * H * 8) {    // 12800: W1 relayout
        int k  = n - 25 * D * 8;
        int t  = k >> 7;
        int r  = k & 127;
        int j  = r >> 3;
        int ip = r & 7;
        g_W1T2[k] = make_float2(W1[(size_t)(t * 16 + 2 * ip) * H + j],
                                W1[(size_t)(t * 16 + 2 * ip + 1) * H + j]);
    }
}

// ---------------- main: 1 CTA = 8 batches; h1/h2 in registers + shuffles ----
__global__ __launch_bounds__(THREADS, 4)
void basemodel_kernel(const float* __restrict__ x,
                      const float* __restrict__ log_alpha,
                      const float* __restrict__ noise,
                      const float* __restrict__ b0,
                      const float* __restrict__ b1,
                      const float* __restrict__ W2,
                      const float* __restrict__ b2,
                      float* __restrict__ out)
{
    __shared__ unsigned short s_mask[D * D];   // [(g*100+t)*4 + jj], 8 bits used
    __shared__ float4 s_xa[D];                 // batches 0..3
    __shared__ float4 s_xb[D];                 // batches 4..7

    const int tid = threadIdx.x;
    const int b0i = blockIdx.x * BPB;

    // ---- Phase A: Gumbel-hard mask bits (forward value of ST estimator) ----
    {
        const float* nz = noise + (size_t)b0i * D * D;
        for (int m = tid; m < D * D; m += THREADS) {
            int j = m / D;
            int t = m - j * D;
            float la = log_alpha[m];
            unsigned bits = 0;
            #pragma unroll
            for (int c = 0; c < 8; ++c)
                bits |= ((la + nz[(size_t)c * D * D + m]) > 0.0f) ? (1u << c) : 0u;
            if (j == t) bits = 0;               // no-self-loop mask
            s_mask[((j >> 2) * D + t) * 4 + (j & 3)] = (unsigned short)bits;
        }
        if (tid < D) {
            int j = tid;
            s_xa[j] = make_float4(x[(size_t)(b0i + 0) * D + j], x[(size_t)(b0i + 1) * D + j],
                                  x[(size_t)(b0i + 2) * D + j], x[(size_t)(b0i + 3) * D + j]);
            s_xb[j] = make_float4(x[(size_t)(b0i + 4) * D + j], x[(size_t)(b0i + 5) * D + j],
                                  x[(size_t)(b0i + 6) * D + j], x[(size_t)(b0i + 7) * D + j]);
        }
    }
    __syncthreads();

    float* outbase = out + (size_t)b0i * D * P;

    // ---- Passes: unit u = (t, ip); 8 lanes per t, ip owns i = {2ip, 2ip+1} ----
    // Trip count is warp-uniform (800 = 3*256 + 32; 4th pass = warp 0 exactly),
    // so full-mask shuffles below are legal.
    for (int u = tid; u < D * 8; u += THREADS) {
        const int t  = u >> 3;
        const int ip = u & 7;

        // ---- Phase B: layer0 -> h1 in regs ----
        float aL[8], aH[8];
        #pragma unroll
        for (int c = 0; c < 8; ++c) { aL[c] = 0.0f; aH[c] = 0.0f; }

        #pragma unroll 5
        for (int g = 0; g < 25; ++g) {
            uint2 mw = *(const uint2*)&s_mask[(g * D + t) * 4];
            const float4* wp = &g_W0T8[(size_t)((g * D + t) * 8 + ip) * 2];
            float4 wlo = wp[0];
            float4 whi = wp[1];
            unsigned mb[4] = { mw.x & 0xFFFFu, mw.x >> 16, mw.y & 0xFFFFu, mw.y >> 16 };
            float wl[4] = { wlo.x, wlo.y, wlo.z, wlo.w };
            float wh[4] = { whi.x, whi.y, whi.z, whi.w };
            #pragma unroll
            for (int jj = 0; jj < 4; ++jj) {
                float4 xa = s_xa[4 * g + jj];
                float4 xb = s_xb[4 * g + jj];
                float xv[8] = { xa.x, xa.y, xa.z, xa.w, xb.x, xb.y, xb.z, xb.w };
                #pragma unroll
                for (int c = 0; c < 8; ++c) {
                    float xm = (mb[jj] & (1u << c)) ? xv[c] : 0.0f;
                    aL[c] = fmaf(wl[jj], xm, aL[c]);
                    aH[c] = fmaf(wh[jj], xm, aH[c]);
                }
            }
        }
        {
            float2 bb = *(const float2*)&b0[t * H + 2 * ip];
            #pragma unroll
            for (int c = 0; c < 8; ++c) {
                aL[c] = leaky1(aL[c] + bb.x);   // h1 for i = 2ip
                aH[c] = leaky1(aH[c] + bb.y);   // h1 for i = 2ip+1
            }
        }

        // ---- Phase C: layer1 via width-8 shuffles ----
        float cL[8], cH[8];
        #pragma unroll
        for (int c = 0; c < 8; ++c) { cL[c] = 0.0f; cH[c] = 0.0f; }
        #pragma unroll
        for (int j = 0; j < H; ++j) {
            float2 w1 = g_W1T2[(t * H + j) * 8 + ip];
            #pragma unroll
            for (int c = 0; c < 8; ++c) {
                float hv = __shfl_sync(0xffffffffu,
                                       (j & 1) ? aH[c] : aL[c], j >> 1, 8);
                cL[c] = fmaf(w1.x, hv, cL[c]);
                cH[c] = fmaf(w1.y, hv, cH[c]);
            }
        }
        {
            float2 bb = *(const float2*)&b1[t * H + 2 * ip];
            #pragma unroll
            for (int c = 0; c < 8; ++c) {
                cL[c] = leaky1(cL[c] + bb.x);   // h2 for i = 2ip
                cH[c] = leaky1(cH[c] + bb.y);   // h2 for i = 2ip+1
            }
        }

        // ---- Phase D: output layer, butterfly reduce over 8 lanes ----
        float2 w20 = *(const float2*)&W2[(size_t)t * P * H + 0 * H + 2 * ip];
        float2 w21 = *(const float2*)&W2[(size_t)t * P * H + 1 * H + 2 * ip];
        float pa[8], pb[8];
        #pragma unroll
        for (int c = 0; c < 8; ++c) {
            pa[c] = fmaf(w20.y, cH[c], w20.x * cL[c]);
            pb[c] = fmaf(w21.y, cH[c], w21.x * cL[c]);
        }
        #pragma unroll
        for (int s = 1; s < 8; s <<= 1) {
            #pragma unroll
            for (int c = 0; c < 8; ++c) {
                pa[c] += __shfl_xor_sync(0xffffffffu, pa[c], s, 8);
                pb[c] += __shfl_xor_sync(0xffffffffu, pb[c], s, 8);
            }
        }
        // after the butterfly all 8 lanes hold identical sums; lane ip emits batch b0i+ip
        float oa = pa[0], ob = pb[0];
        #pragma unroll
        for (int k = 1; k < 8; ++k) {
            if (ip == k) { oa = pa[k]; ob = pb[k]; }
        }
        float2 bb2 = *(const float2*)&b2[t * P];
        float2 o   = make_float2(oa + bb2.x, ob + bb2.y);
        *(float2*)&outbase[(size_t)ip * D * P + t * P] = o;
    }
}

extern "C" void kernel_launch(void* const* d_in, const int* in_sizes, int n_in,
                              void* d_out, int out_size)
{
    const float* x         = (const float*)d_in[0];
    const float* log_alpha = (const float*)d_in[1];
    const float* noise     = (const float*)d_in[2];
    const float* W0        = (const float*)d_in[3];
    const float* b0        = (const float*)d_in[4];
    const float* W1        = (const float*)d_in[5];
    const float* b1        = (const float*)d_in[6];
    const float* W2        = (const float*)d_in[7];
    const float* b2        = (const float*)d_in[8];
    float* out             = (float*)d_out;

    const int prep_n = 25 * D * 8 + D * H * 8;           // 32800
    prep_kernel<<<(prep_n + THREADS - 1) / THREADS, THREADS>>>(W0, W1);

    basemodel_kernel<<<GRID, THREADS>>>(
        x, log_alpha, noise, b0, b1, W2, b2, out);
}